// round 16
// baseline (speedup 1.0000x reference)
#include <cuda_runtime.h>
#include <cuda_fp16.h>
#include <cstdint>
#include <math.h>

#define Bb 4
#define Nn 4096
#define Dd 256
#define Pp 64
#define Hh 1024
#define NCc 256
#define BN (Bb*Nn)

// ---------------- device scratch ----------------
__device__ float g_Qf[(size_t)BN*64];
__device__ float g_Kf[(size_t)BN*64];
__device__ __half g_Qh[(size_t)BN*64];
__device__ __half g_Kh[(size_t)BN*64];
__device__ __half g_Ph[(size_t)BN*64];
__device__ __half g_WhT[(size_t)Hh*Dd];
__device__ __half g_Xh[(size_t)BN*Dd];
__device__ float g_INC[(size_t)BN*Dd];
__device__ float g_dot[BN], g_na[BN], g_nb[BN];
__device__ int   g_hitcnt[BN];
__device__ int   g_hitlist[BN*32];

// ---------------- helpers ----------------
__device__ __forceinline__ uint32_t smem_u32(const void* p){
    uint32_t a;
    asm("{ .reg .u64 t; cvta.to.shared.u64 t, %1; cvt.u32.u64 %0, t; }" : "=r"(a) : "l"(p));
    return a;
}
__device__ __forceinline__ void ldmA(uint32_t tile, int m0, int kc, int stride, uint32_t* a){
    int lane = threadIdx.x & 31;
    uint32_t addr = tile + (uint32_t)(m0 + (lane & 15))*stride + (uint32_t)kc*32 + ((lane >> 4)*16);
    asm volatile("ldmatrix.sync.aligned.m8n8.x4.shared.b16 {%0,%1,%2,%3}, [%4];"
        : "=r"(a[0]),"=r"(a[1]),"=r"(a[2]),"=r"(a[3]) : "r"(addr));
}
__device__ __forceinline__ void ldmB4(uint32_t tile, int n0, int kc, int stride, uint32_t* b){
    int lane = threadIdx.x & 31;
    int g = lane >> 3;
    uint32_t addr = tile + (uint32_t)(n0 + ((g & 2) ? 8 : 0) + (lane & 7))*stride
                  + (uint32_t)kc*32 + ((g & 1)*16);
    asm volatile("ldmatrix.sync.aligned.m8n8.x4.shared.b16 {%0,%1,%2,%3}, [%4];"
        : "=r"(b[0]),"=r"(b[1]),"=r"(b[2]),"=r"(b[3]) : "r"(addr));
}
__device__ __forceinline__ void mma_h(float* c, const uint32_t* a, const uint32_t* b){
    asm volatile("mma.sync.aligned.m16n8k16.row.col.f32.f16.f16.f32 "
        "{%0,%1,%2,%3}, {%4,%5,%6,%7}, {%8,%9}, {%0,%1,%2,%3};"
        : "+f"(c[0]),"+f"(c[1]),"+f"(c[2]),"+f"(c[3])
        : "r"(a[0]),"r"(a[1]),"r"(a[2]),"r"(a[3]), "r"(b[0]),"r"(b[1]));
}
#define CP_COMMIT() asm volatile("cp.async.commit_group;" ::: "memory")
#define CP_WAIT1()  asm volatile("cp.async.wait_group 1;" ::: "memory")
#define CP_WAIT0()  asm volatile("cp.async.wait_group 0;" ::: "memory")

// Branchless sorted-insert into descending top-8 (static indices only).
#define INS8(V, I, val, col) do { \
    if ((val) > V[7]){ \
        V[7] = (val); I[7] = (col); \
        _Pragma("unroll") \
        for (int _s = 7; _s > 0; _s--){ \
            bool _sw = V[_s] > V[_s-1]; \
            float _tv = _sw ? V[_s-1] : V[_s]; \
            int   _ti = _sw ? I[_s-1] : I[_s]; \
            V[_s-1] = _sw ? V[_s] : V[_s-1]; \
            I[_s-1] = _sw ? I[_s] : I[_s-1]; \
            V[_s] = _tv; I[_s] = _ti; \
        } \
    } } while(0)

// ---------------- kernel 1: projections (smem-staged W) ------------------
#define PROJ_BLOCKS (BN/32)
#define WH_BLOCKS   ((Dd*Hh)/256)
#define PJ_AS 0
#define PJ_W  32768
#define PJ_INV 81920
#define PJ_TOT 82048

__global__ __launch_bounds__(256) void proj_kernel(
    const float* __restrict__ actions,
    const float* __restrict__ Wq, const float* __restrict__ bq,
    const float* __restrict__ Wk, const float* __restrict__ bk,
    const float* __restrict__ Wc, const float* __restrict__ bc,
    const float* __restrict__ Wh)
{
    extern __shared__ char psm[];
    int tid = threadIdx.x;

    if (blockIdx.x >= PROJ_BLOCKS){
        int idx = (blockIdx.x - PROJ_BLOCKS)*256 + tid;
        int k = idx >> 10, n = idx & 1023;
        g_WhT[(size_t)n*Dd + k] = __float2half(Wh[idx]);
        return;
    }

    float* As   = (float*)(psm + PJ_AS);
    float* Wsm  = (float*)(psm + PJ_W);
    float* invn = (float*)(psm + PJ_INV);
    float* Qs = As;
    float* Ks = As + 32*65;
    float* Ps = As + 64*65;
    int row0 = blockIdx.x * 32;

    for (int idx = tid; idx < 32*Dd; idx += 256)
        As[idx] = actions[(size_t)row0*Dd + idx];

    int p = tid & 63, g = tid >> 6;
    float aq[8], ak[8], ac[8];
#pragma unroll
    for (int i = 0; i < 8; i++){ aq[i]=0.f; ak[i]=0.f; ac[i]=0.f; }

    for (int c = 0; c < 4; c++){
        __syncthreads();
        const float4* Wq4 = (const float4*)(Wq + c*64*Pp);
        const float4* Wk4 = (const float4*)(Wk + c*64*Pp);
        const float4* Wc4 = (const float4*)(Wc + c*64*Pp);
        float4* W0 = (float4*)Wsm;
        float4* W1 = (float4*)(Wsm + 4096);
        float4* W2 = (float4*)(Wsm + 8192);
#pragma unroll
        for (int i = tid; i < 1024; i += 256){
            W0[i] = Wq4[i];
            W1[i] = Wk4[i];
            W2[i] = Wc4[i];
        }
        __syncthreads();
#pragma unroll 4
        for (int d2 = 0; d2 < 64; d2++){
            int d = c*64 + d2;
            float wq = Wsm[d2*64 + p];
            float wk = Wsm[4096 + d2*64 + p];
            float wc = Wsm[8192 + d2*64 + p];
#pragma unroll
            for (int i = 0; i < 8; i++){
                float a = As[(g*8+i)*Dd + d];
                aq[i] = fmaf(a, wq, aq[i]);
                ak[i] = fmaf(a, wk, ak[i]);
                ac[i] = fmaf(a, wc, ac[i]);
            }
        }
    }
    float vbq = bq[p], vbk = bk[p], vbc = bc[p];
    __syncthreads();
#pragma unroll
    for (int i = 0; i < 8; i++){
        int r = g*8+i;
        Qs[r*65+p] = aq[i]+vbq;
        Ks[r*65+p] = ak[i]+vbk;
        Ps[r*65+p] = ac[i]+vbc;
    }
    __syncthreads();
    if (tid < 32){
        float s = 0.f;
        for (int j = 0; j < 64; j++){ float v = Ps[tid*65+j]; s = fmaf(v,v,s); }
        invn[tid] = 1.0f / fmaxf(sqrtf(s), 1e-12f);
        g_hitcnt[row0 + tid] = 0;
    }
    __syncthreads();
    for (int idx = tid; idx < 32*64; idx += 256){
        int r = idx >> 6, pp = idx & 63;
        size_t o = (size_t)(row0 + r)*64 + pp;
        float q = Qs[r*65+pp], k = Ks[r*65+pp], pn = Ps[r*65+pp]*invn[r];
        g_Qf[o] = q; g_Kf[o] = k;
        g_Qh[o] = __float2half(q);
        g_Kh[o] = __float2half(k);
        g_Ph[o] = __float2half(pn);
    }
}

// ---------------- kernel 2: graph (R10 M=64 tiling, 2 CTA/SM) ------------
#define GSR 144
#define GA_QH 0
#define GA_PH 9216
#define GB 18432
#define GB_BUF 36864
#define GB_KH 0
#define GB_PH 18432
#define G_TOT 92160
#define G_CANDI 0
#define G_MV 16384
#define G_MI 24576
#define G_TOPW 32768
#define G_TOPI 34816

__device__ __forceinline__ void cp_tile64(uint32_t sb, int dst, const __half* src, int tid){
    const char* s = (const char*)src;
#pragma unroll
    for (int i = tid; i < 512; i += 256){
        int row = i >> 3, ch = i & 7;
        uint32_t d = sb + dst + row*GSR + ch*16;
        asm volatile("cp.async.cg.shared.global [%0], [%1], 16;" :: "r"(d), "l"(s + i*16));
    }
}
__device__ __forceinline__ void cp_tile128(uint32_t sb, int dst, const __half* src, int tid){
    const char* s = (const char*)src;
#pragma unroll
    for (int i = tid; i < 1024; i += 256){
        int row = i >> 3, ch = i & 7;
        uint32_t d = sb + dst + row*GSR + ch*16;
        asm volatile("cp.async.cg.shared.global [%0], [%1], 16;" :: "r"(d), "l"(s + i*16));
    }
}

__global__ __launch_bounds__(256,2) void graph_kernel(const float* __restrict__ states)
{
    extern __shared__ char sm[];
    uint32_t sb = smem_u32(sm);
    int tid = threadIdx.x, wid = tid >> 5, lane = tid & 31;
    int bb = blockIdx.y, n0 = blockIdx.x * 64;
    size_t bofs = (size_t)bb*Nn*64;
    int tmin_sim = n0 >> 7;

    cp_tile64(sb, GA_QH, g_Qh + bofs + (size_t)n0*64, tid);
    cp_tile64(sb, GA_PH, g_Ph + bofs + (size_t)n0*64, tid);
    cp_tile128(sb, GB + GB_KH, g_Kh + bofs, tid);
    if (0 >= tmin_sim) cp_tile128(sb, GB + GB_PH, g_Ph + bofs, tid);
    CP_COMMIT();
    {
        size_t mofs = bofs + (size_t)128*64;
        cp_tile128(sb, GB + GB_BUF + GB_KH, g_Kh + mofs, tid);
        if (1 >= tmin_sim) cp_tile128(sb, GB + GB_BUF + GB_PH, g_Ph + mofs, tid);
        CP_COMMIT();
    }

    int wm = (wid & 3)*16, wn0 = (wid >> 2)*64, wng = wid >> 2;
    int rql = lane >> 2, cq = (lane & 3)*2, j4 = lane & 3;

    float v0[8], v1[8]; int i0[8], i1[8];
#pragma unroll
    for (int j = 0; j < 8; j++){ v0[j]=-1e30f; v1[j]=-1e30f; i0[j]=0; i1[j]=0; }

    for (int t = 0; t < Nn/128; t++){
        int buf = t & 1;
        if (t + 1 < Nn/128) CP_WAIT1(); else CP_WAIT0();
        __syncthreads();
        uint32_t bB = sb + GB + buf*GB_BUF;

        // ---- pass 1: scores = Qh . Kh ----
        float acc[8][4];
#pragma unroll
        for (int nt = 0; nt < 8; nt++)
#pragma unroll
            for (int e = 0; e < 4; e++) acc[nt][e] = 0.f;
#pragma unroll
        for (int kc = 0; kc < 4; kc++){
            uint32_t ah[4];
            ldmA(sb + GA_QH, wm, kc, GSR, ah);
            uint32_t bf[4][4];
#pragma unroll
            for (int p = 0; p < 4; p++) ldmB4(bB + GB_KH, wn0 + p*16, kc, GSR, bf[p]);
#pragma unroll
            for (int nt = 0; nt < 8; nt++) mma_h(acc[nt], ah, &bf[nt>>1][(nt&1)*2]);
        }
        {
            float t0 = -1e30f, t1 = -1e30f;
#pragma unroll
            for (int nt = 0; nt < 8; nt++){
                t0 = fmaxf(t0, fmaxf(acc[nt][0], acc[nt][1]));
                t1 = fmaxf(t1, fmaxf(acc[nt][2], acc[nt][3]));
            }
            if (t0 > v0[7]){
#pragma unroll
                for (int nt = 0; nt < 8; nt++){
                    int cb = t*128 + wn0 + nt*8 + cq;
                    INS8(v0, i0, acc[nt][0], cb);
                    INS8(v0, i0, acc[nt][1], cb+1);
                }
            }
            if (t1 > v1[7]){
#pragma unroll
                for (int nt = 0; nt < 8; nt++){
                    int cb = t*128 + wn0 + nt*8 + cq;
                    INS8(v1, i1, acc[nt][2], cb);
                    INS8(v1, i1, acc[nt][3], cb+1);
                }
            }
        }

        // ---- pass 2: sim = Ph . Ph (upper triangle, mirrored) ----
        if (t >= tmin_sim){
#pragma unroll
            for (int nt = 0; nt < 8; nt++)
#pragma unroll
                for (int e = 0; e < 4; e++) acc[nt][e] = 0.f;
#pragma unroll
            for (int kc = 0; kc < 4; kc++){
                uint32_t ah[4];
                ldmA(sb + GA_PH, wm, kc, GSR, ah);
                uint32_t bf[4][4];
#pragma unroll
                for (int p = 0; p < 4; p++) ldmB4(bB + GB_PH, wn0 + p*16, kc, GSR, bf[p]);
#pragma unroll
                for (int nt = 0; nt < 8; nt++) mma_h(acc[nt], ah, &bf[nt>>1][(nt&1)*2]);
            }
#pragma unroll
            for (int nt = 0; nt < 8; nt++)
#pragma unroll
                for (int e = 0; e < 4; e++){
                    if (acc[nt][e] > 0.7f){
                        int row = n0 + wm + rql + ((e >= 2) ? 8 : 0);
                        int col = t*128 + wn0 + nt*8 + cq + (e & 1);
                        if (col >= row){
                            int hr = bb*Nn + row;
                            int s1 = atomicAdd(&g_hitcnt[hr], 1);
                            if (s1 < 32) g_hitlist[(size_t)hr*32 + s1] = col;
                            if (col > row){
                                int hc = bb*Nn + col;
                                int s2 = atomicAdd(&g_hitcnt[hc], 1);
                                if (s2 < 32) g_hitlist[(size_t)hc*32 + s2] = row;
                            }
                        }
                    }
                }
        }
        __syncthreads();

        if (t + 2 < Nn/128){
            size_t mofs = bofs + (size_t)(t+2)*128*64;
            cp_tile128(sb, GB + buf*GB_BUF + GB_KH, g_Kh + mofs, tid);
            if (t + 2 >= tmin_sim) cp_tile128(sb, GB + buf*GB_BUF + GB_PH, g_Ph + mofs, tid);
            CP_COMMIT();
        }
    }
    __syncthreads();

    // ---- dump candidates: 8 slices/row x 8 = 64 per row ----
    int* candI = (int*)(sm + G_CANDI);
    {
        int r0 = wm + rql, r1 = wm + rql + 8;
        int slice = wng*4 + j4;
#pragma unroll
        for (int s = 0; s < 8; s++){
            candI[r0*64 + slice*8 + s] = i0[s];
            candI[r1*64 + slice*8 + s] = i1[s];
        }
    }
    __syncthreads();

    // ---- exact fp32 rescore: 4 threads/row x 16 candidates ----
    float* mergeV = (float*)(sm + G_MV);
    int*   mergeI = (int*)(sm + G_MI);
    {
        int row = tid >> 2, sub = tid & 3;
        const float4* Q4 = (const float4*)(g_Qf + bofs + (size_t)(n0 + row)*64);
        float q[64];
#pragma unroll
        for (int i = 0; i < 16; i++){
            float4 v = Q4[i];
            q[4*i] = v.x; q[4*i+1] = v.y; q[4*i+2] = v.z; q[4*i+3] = v.w;
        }
        float tv[8]; int ti8[8];
#pragma unroll
        for (int j = 0; j < 8; j++){ tv[j] = -1e30f; ti8[j] = 0; }
#pragma unroll
        for (int c = 0; c < 16; c++){
            int col = candI[row*64 + sub*16 + c];
            const float4* K4 = (const float4*)(g_Kf + bofs + (size_t)col*64);
            float a2 = 0.f;
#pragma unroll
            for (int i = 0; i < 16; i++){
                float4 kv = K4[i];
                a2 = fmaf(q[4*i],   kv.x, a2);
                a2 = fmaf(q[4*i+1], kv.y, a2);
                a2 = fmaf(q[4*i+2], kv.z, a2);
                a2 = fmaf(q[4*i+3], kv.w, a2);
            }
            a2 *= 0.125f;
            INS8(tv, ti8, a2, col);
        }
#pragma unroll
        for (int s = 0; s < 8; s++){
            mergeV[row*32 + sub*8 + s] = tv[s];
            mergeI[row*32 + sub*8 + s] = ti8[s];
        }
    }
    __syncthreads();

    // ---- final merge + softmax (64 threads) ----
    float* topW = (float*)(sm + G_TOPW);
    int*   topI = (int*)(sm + G_TOPI);
    if (tid < 64){
        float tv[8]; int ti8[8];
#pragma unroll
        for (int j = 0; j < 8; j++){ tv[j] = -1e30f; ti8[j] = 0; }
#pragma unroll
        for (int c = 0; c < 32; c++){
            float mv = mergeV[tid*32 + c];
            int  mi = mergeI[tid*32 + c];
            INS8(tv, ti8, mv, mi);
        }
        float mx = tv[0];
        float e[8], ssum = 0.f;
#pragma unroll
        for (int j = 0; j < 8; j++){ e[j] = __expf(tv[j] - mx); ssum += e[j]; }
        float inv = 1.f / ssum;
#pragma unroll
        for (int j = 0; j < 8; j++){ topW[tid*8+j] = e[j]*inv; topI[tid*8+j] = ti8[j]; }
    }
    __syncthreads();

    // ---- gather incoming (8 warps x 8 rows) ----
    const float* Sb = states + (size_t)bb*Nn*Dd;
    for (int rr = 0; rr < 8; rr++){
        int r = wid*8 + rr;
        float w8[8]; int i8[8];
#pragma unroll
        for (int j = 0; j < 8; j++){ w8[j] = topW[r*8+j]; i8[j] = topI[r*8+j]; }
        float* Ig = g_INC + ((size_t)bb*Nn + n0 + r)*Dd;
#pragma unroll
        for (int dd = 0; dd < 8; dd++){
            int d = lane + dd*32;
            float a2 = 0.f;
#pragma unroll
            for (int j = 0; j < 8; j++) a2 = fmaf(w8[j], Sb[(size_t)i8[j]*Dd + d], a2);
            Ig[d] = a2;
        }
    }
}

// ---------------- kernel 3a: phase-1 gather + X (fp16) ----------------
__global__ __launch_bounds__(256) void hdc_a(float* __restrict__ out_states){
    int tid = threadIdx.x, wid = tid >> 5, lane = tid & 31;
    int row0 = blockIdx.x * 64;
    int bb = row0 / Nn;
    for (int r8 = 0; r8 < 8; r8++){
        int row = row0 + wid*8 + r8;
        int cnt = g_hitcnt[row];
        int lim = cnt < 32 ? cnt : 32;
        const int* hl = g_hitlist + (size_t)row*32;
        float comb[8];
#pragma unroll
        for (int i = 0; i < 8; i++) comb[i] = 0.f;
        for (int j = 0; j < lim; j++){
            const float* src = g_INC + ((size_t)bb*Nn + hl[j])*Dd;
#pragma unroll
            for (int i = 0; i < 8; i++) comb[i] += src[lane + i*32];
        }
        const float* inc = g_INC + (size_t)row*Dd;
        float inv = 0.2f / ((float)cnt + 1e-8f);
#pragma unroll
        for (int i = 0; i < 8; i++){
            int d = lane + i*32;
            float ov = 0.8f*inc[d] + comb[i]*inv;
            out_states[(size_t)row*Dd + d] = ov;
            g_Xh[(size_t)row*Dd + d] = __float2half(ov);
        }
    }
    if (tid < 64){
        g_dot[row0+tid] = 0.f; g_na[row0+tid] = 0.f; g_nb[row0+tid] = 0.f;
    }
}

// ---------------- kernel 3b: Wh GEMM + coalesced fused episodic ----------
#define SR 144
#define HB_BUFSZ 27648
#define HB_AH 0
#define HB_BH 18432
#define HB_TOT 55296

__device__ __forceinline__ void cp_rows(uint32_t sb, int dst, const __half* src,
                                        int nrows, size_t srcstride, int tid){
    int total = nrows*8;
    for (int i = tid; i < total; i += 256){
        int row = i >> 3, ch = i & 7;
        uint32_t d = sb + dst + row*SR + ch*16;
        const char* s = (const char*)(src + (size_t)row*srcstride) + ch*16;
        asm volatile("cp.async.cg.shared.global [%0], [%1], 16;" :: "r"(d), "l"(s));
    }
}

__global__ __launch_bounds__(256,3) void hdc_b(
    const float* __restrict__ episodic,
    const float* __restrict__ bh,
    const float* __restrict__ keys, const float* __restrict__ pcodes,
    const int* __restrict__ step,
    float* __restrict__ out_epi)
{
    extern __shared__ char sm[];
    uint32_t sb = smem_u32(sm);
    int tid = threadIdx.x, wid = tid >> 5, lane = tid & 31;
    int row0 = blockIdx.x * 128;
    int c0   = blockIdx.y * 64;
    int prow = ((step[0] % NCc) + NCc) % NCc;
    const float* posr = pcodes + (size_t)prow*Hh;

    const __half* Xh = g_Xh + (size_t)row0*Dd;
    const __half* Wh = g_WhT + (size_t)c0*Dd;

    cp_rows(sb, HB_AH, Xh,      128, Dd, tid);
    cp_rows(sb, HB_BH, Wh,      64,  Dd, tid);
    CP_COMMIT();
    cp_rows(sb, HB_BUFSZ + HB_AH, Xh + 64, 128, Dd, tid);
    cp_rows(sb, HB_BUFSZ + HB_BH, Wh + 64, 64,  Dd, tid);
    CP_COMMIT();

    int wm = wid*16;
    int rql = lane >> 2, cq = (lane & 3)*2;

    float acc[8][4];
#pragma unroll
    for (int nt = 0; nt < 8; nt++)
#pragma unroll
        for (int e = 0; e < 4; e++) acc[nt][e] = 0.f;

    for (int c = 0; c < 4; c++){
        int buf = c & 1;
        if (c + 1 < 4) CP_WAIT1(); else CP_WAIT0();
        __syncthreads();
        uint32_t aH = sb + buf*HB_BUFSZ + HB_AH;
        uint32_t bH = sb + buf*HB_BUFSZ + HB_BH;
#pragma unroll
        for (int kc = 0; kc < 4; kc++){
            uint32_t ah[4];
            ldmA(aH, wm, kc, SR, ah);
            uint32_t bfh[4][4];
#pragma unroll
            for (int p = 0; p < 4; p++) ldmB4(bH, p*16, kc, SR, bfh[p]);
#pragma unroll
            for (int nt = 0; nt < 8; nt++) mma_h(acc[nt], ah, &bfh[nt>>1][(nt&1)*2]);
        }
        __syncthreads();
        if (c + 2 < 4){
            int koff = (c+2)*64;
            cp_rows(sb, buf*HB_BUFSZ + HB_AH, Xh + koff, 128, Dd, tid);
            cp_rows(sb, buf*HB_BUFSZ + HB_BH, Wh + koff, 64,  Dd, tid);
            CP_COMMIT();
        }
    }

    // ---- stage accumulators to smem (GEMM buffers now dead) ----
    float* Acc = (float*)sm;                 // [128][66] = 33792 B < 55296
#pragma unroll
    for (int nt = 0; nt < 8; nt++){
        int cl = nt*8 + cq;
        int r0l = wm + rql;
        Acc[r0l*66 + cl]       = acc[nt][0];
        Acc[r0l*66 + cl + 1]   = acc[nt][1];
        Acc[(r0l+8)*66 + cl]     = acc[nt][2];
        Acc[(r0l+8)*66 + cl + 1] = acc[nt][3];
    }
    __syncthreads();

    // ---- coalesced epilogue: warp owns 16 rows, lanes cover 64 cols ----
    int c = c0 + lane*2;
    float2 bh2  = *(const float2*)(bh + c);
    float2 pos2 = *(const float2*)(posr + c);
    for (int r = wid*16; r < wid*16 + 16; r++){
        int grow = row0 + r;
        int nk = grow & (Nn - 1);
        float a0v = Acc[r*66 + lane*2];
        float a1v = Acc[r*66 + lane*2 + 1];
        float y0 = 6.0f*(a0v + bh2.x);
        float y1 = 6.0f*(a1v + bh2.y);
        float h0 = 1.0f - 2.0f/(__expf(y0) + 1.0f);
        float h1 = 1.0f - 2.0f/(__expf(y1) + 1.0f);
        float2 ky = *(const float2*)(keys + (size_t)nk*Hh + c);
        float pe0 = h0*ky.x, pe1 = h1*ky.y;
        float2 ep = *(const float2*)(episodic + (size_t)grow*Hh + c);
        float ne0 = 0.95f*ep.x + 0.05f*pe0*pos2.x;
        float ne1 = 0.95f*ep.y + 0.05f*pe1*pos2.y;
        *(float2*)(out_epi + (size_t)grow*Hh + c) = make_float2(ne0, ne1);
        float dt = fmaf(ne0, pe0, ne1*pe1);
        float na = fmaf(ne0, ne0, ne1*ne1);
        float nb = fmaf(pe0, pe0, pe1*pe1);
#pragma unroll
        for (int off = 16; off; off >>= 1){
            dt += __shfl_xor_sync(0xffffffffu, dt, off);
            na += __shfl_xor_sync(0xffffffffu, na, off);
            nb += __shfl_xor_sync(0xffffffffu, nb, off);
        }
        if (lane == 0){
            atomicAdd(&g_dot[grow], dt);
            atomicAdd(&g_na[grow], na);
            atomicAdd(&g_nb[grow], nb);
        }
    }
}

// ---------------- kernel 3c: out_sim finisher ----------------
__global__ __launch_bounds__(256) void hdc_c(float* __restrict__ out_sim){
    int i = blockIdx.x*256 + threadIdx.x;
    out_sim[i] = g_dot[i] / (fmaxf(sqrtf(g_na[i]), 1e-8f)*fmaxf(sqrtf(g_nb[i]), 1e-8f));
}

// ---------------- launch ----------------
extern "C" void kernel_launch(void* const* d_in, const int* in_sizes, int n_in,
                              void* d_out, int out_size)
{
    (void)in_sizes; (void)n_in; (void)out_size;
    const float* states   = (const float*)d_in[0];
    const float* actions  = (const float*)d_in[1];
    const float* episodic = (const float*)d_in[2];
    const float* Wq = (const float*)d_in[3];  const float* bq = (const float*)d_in[4];
    const float* Wk = (const float*)d_in[5];  const float* bk = (const float*)d_in[6];
    const float* Wc = (const float*)d_in[7];  const float* bc = (const float*)d_in[8];
    const float* Wh = (const float*)d_in[9];  const float* bh = (const float*)d_in[10];
    const float* keys   = (const float*)d_in[11];
    const float* pcodes = (const float*)d_in[12];
    const int*   step   = (const int*)d_in[13];

    float* out = (float*)d_out;
    float* o_states = out;
    float* o_epi    = out + (size_t)BN*Dd;
    float* o_sim    = out + (size_t)BN*Dd + (size_t)BN*Hh;

    cudaFuncSetAttribute(proj_kernel, cudaFuncAttributeMaxDynamicSharedMemorySize, PJ_TOT);
    proj_kernel<<<PROJ_BLOCKS + WH_BLOCKS, 256, PJ_TOT>>>(actions, Wq, bq, Wk, bk, Wc, bc, Wh);

    cudaFuncSetAttribute(graph_kernel, cudaFuncAttributeMaxDynamicSharedMemorySize, G_TOT);
    graph_kernel<<<dim3(Nn/64, Bb), 256, G_TOT>>>(states);

    hdc_a<<<BN/64, 256>>>(o_states);

    cudaFuncSetAttribute(hdc_b, cudaFuncAttributeMaxDynamicSharedMemorySize, HB_TOT);
    hdc_b<<<dim3(BN/128, Hh/64), 256, HB_TOT>>>(episodic, bh, keys, pcodes, step, o_epi);

    hdc_c<<<BN/256, 256>>>(o_sim);
}

// round 17
// speedup vs baseline: 1.1405x; 1.1405x over previous
#include <cuda_runtime.h>
#include <cuda_fp16.h>
#include <cstdint>
#include <math.h>

#define Bb 4
#define Nn 4096
#define Dd 256
#define Pp 64
#define Hh 1024
#define NCc 256
#define BN (Bb*Nn)

// ---------------- device scratch ----------------
__device__ float g_Qf[(size_t)BN*64];
__device__ float g_Kf[(size_t)BN*64];
__device__ __half g_Qh[(size_t)BN*64];
__device__ __half g_Kh[(size_t)BN*64];
__device__ __half g_Ph[(size_t)BN*64];
__device__ __half g_WhT[(size_t)Hh*Dd];
__device__ __half g_Xh[(size_t)BN*Dd];
__device__ float g_INC[(size_t)BN*Dd];
__device__ float g_dot[BN], g_na[BN], g_nb[BN];
__device__ int   g_hitcnt[BN];
__device__ int   g_hitlist[BN*32];

// ---------------- helpers ----------------
__device__ __forceinline__ uint32_t smem_u32(const void* p){
    uint32_t a;
    asm("{ .reg .u64 t; cvta.to.shared.u64 t, %1; cvt.u32.u64 %0, t; }" : "=r"(a) : "l"(p));
    return a;
}
__device__ __forceinline__ void ldmA(uint32_t tile, int m0, int kc, int stride, uint32_t* a){
    int lane = threadIdx.x & 31;
    uint32_t addr = tile + (uint32_t)(m0 + (lane & 15))*stride + (uint32_t)kc*32 + ((lane >> 4)*16);
    asm volatile("ldmatrix.sync.aligned.m8n8.x4.shared.b16 {%0,%1,%2,%3}, [%4];"
        : "=r"(a[0]),"=r"(a[1]),"=r"(a[2]),"=r"(a[3]) : "r"(addr));
}
__device__ __forceinline__ void ldmB4(uint32_t tile, int n0, int kc, int stride, uint32_t* b){
    int lane = threadIdx.x & 31;
    int g = lane >> 3;
    uint32_t addr = tile + (uint32_t)(n0 + ((g & 2) ? 8 : 0) + (lane & 7))*stride
                  + (uint32_t)kc*32 + ((g & 1)*16);
    asm volatile("ldmatrix.sync.aligned.m8n8.x4.shared.b16 {%0,%1,%2,%3}, [%4];"
        : "=r"(b[0]),"=r"(b[1]),"=r"(b[2]),"=r"(b[3]) : "r"(addr));
}
__device__ __forceinline__ void mma_h(float* c, const uint32_t* a, const uint32_t* b){
    asm volatile("mma.sync.aligned.m16n8k16.row.col.f32.f16.f16.f32 "
        "{%0,%1,%2,%3}, {%4,%5,%6,%7}, {%8,%9}, {%0,%1,%2,%3};"
        : "+f"(c[0]),"+f"(c[1]),"+f"(c[2]),"+f"(c[3])
        : "r"(a[0]),"r"(a[1]),"r"(a[2]),"r"(a[3]), "r"(b[0]),"r"(b[1]));
}
#define CP_COMMIT() asm volatile("cp.async.commit_group;" ::: "memory")
#define CP_WAIT1()  asm volatile("cp.async.wait_group 1;" ::: "memory")
#define CP_WAIT0()  asm volatile("cp.async.wait_group 0;" ::: "memory")

// Branchless sorted-insert into descending top-8 (static indices only).
#define INS8(V, I, val, col) do { \
    if ((val) > V[7]){ \
        V[7] = (val); I[7] = (col); \
        _Pragma("unroll") \
        for (int _s = 7; _s > 0; _s--){ \
            bool _sw = V[_s] > V[_s-1]; \
            float _tv = _sw ? V[_s-1] : V[_s]; \
            int   _ti = _sw ? I[_s-1] : I[_s]; \
            V[_s-1] = _sw ? V[_s] : V[_s-1]; \
            I[_s-1] = _sw ? I[_s] : I[_s-1]; \
            V[_s] = _tv; I[_s] = _ti; \
        } \
    } } while(0)

// ---------------- kernel 1: projections (smem-staged W) ------------------
#define PROJ_BLOCKS (BN/32)
#define WH_BLOCKS   ((Dd*Hh)/256)
#define PJ_AS 0
#define PJ_W  32768
#define PJ_INV 81920
#define PJ_TOT 82048

__global__ __launch_bounds__(256) void proj_kernel(
    const float* __restrict__ actions,
    const float* __restrict__ Wq, const float* __restrict__ bq,
    const float* __restrict__ Wk, const float* __restrict__ bk,
    const float* __restrict__ Wc, const float* __restrict__ bc,
    const float* __restrict__ Wh)
{
    extern __shared__ char psm[];
    int tid = threadIdx.x;

    if (blockIdx.x >= PROJ_BLOCKS){
        int idx = (blockIdx.x - PROJ_BLOCKS)*256 + tid;
        int k = idx >> 10, n = idx & 1023;
        g_WhT[(size_t)n*Dd + k] = __float2half(Wh[idx]);
        return;
    }

    float* As   = (float*)(psm + PJ_AS);
    float* Wsm  = (float*)(psm + PJ_W);
    float* invn = (float*)(psm + PJ_INV);
    float* Qs = As;
    float* Ks = As + 32*65;
    float* Ps = As + 64*65;
    int row0 = blockIdx.x * 32;

    for (int idx = tid; idx < 32*Dd; idx += 256)
        As[idx] = actions[(size_t)row0*Dd + idx];

    int p = tid & 63, g = tid >> 6;
    float aq[8], ak[8], ac[8];
#pragma unroll
    for (int i = 0; i < 8; i++){ aq[i]=0.f; ak[i]=0.f; ac[i]=0.f; }

    for (int c = 0; c < 4; c++){
        __syncthreads();
        const float4* Wq4 = (const float4*)(Wq + c*64*Pp);
        const float4* Wk4 = (const float4*)(Wk + c*64*Pp);
        const float4* Wc4 = (const float4*)(Wc + c*64*Pp);
        float4* W0 = (float4*)Wsm;
        float4* W1 = (float4*)(Wsm + 4096);
        float4* W2 = (float4*)(Wsm + 8192);
#pragma unroll
        for (int i = tid; i < 1024; i += 256){
            W0[i] = Wq4[i];
            W1[i] = Wk4[i];
            W2[i] = Wc4[i];
        }
        __syncthreads();
#pragma unroll 4
        for (int d2 = 0; d2 < 64; d2++){
            int d = c*64 + d2;
            float wq = Wsm[d2*64 + p];
            float wk = Wsm[4096 + d2*64 + p];
            float wc = Wsm[8192 + d2*64 + p];
#pragma unroll
            for (int i = 0; i < 8; i++){
                float a = As[(g*8+i)*Dd + d];
                aq[i] = fmaf(a, wq, aq[i]);
                ak[i] = fmaf(a, wk, ak[i]);
                ac[i] = fmaf(a, wc, ac[i]);
            }
        }
    }
    float vbq = bq[p], vbk = bk[p], vbc = bc[p];
    __syncthreads();
#pragma unroll
    for (int i = 0; i < 8; i++){
        int r = g*8+i;
        Qs[r*65+p] = aq[i]+vbq;
        Ks[r*65+p] = ak[i]+vbk;
        Ps[r*65+p] = ac[i]+vbc;
    }
    __syncthreads();
    if (tid < 32){
        float s = 0.f;
        for (int j = 0; j < 64; j++){ float v = Ps[tid*65+j]; s = fmaf(v,v,s); }
        invn[tid] = 1.0f / fmaxf(sqrtf(s), 1e-12f);
        g_hitcnt[row0 + tid] = 0;
    }
    __syncthreads();
    for (int idx = tid; idx < 32*64; idx += 256){
        int r = idx >> 6, pp = idx & 63;
        size_t o = (size_t)(row0 + r)*64 + pp;
        float q = Qs[r*65+pp], k = Ks[r*65+pp], pn = Ps[r*65+pp]*invn[r];
        g_Qf[o] = q; g_Kf[o] = k;
        g_Qh[o] = __float2half(q);
        g_Kh[o] = __float2half(k);
        g_Ph[o] = __float2half(pn);
    }
}

// ---------------- kernel 2: graph (M=64 tiling, gated sim checks) --------
#define GSR 144
#define GA_QH 0
#define GA_PH 9216
#define GB 18432
#define GB_BUF 36864
#define GB_KH 0
#define GB_PH 18432
#define G_TOT 92160
#define G_CANDI 0
#define G_MV 16384
#define G_MI 24576
#define G_TOPW 32768
#define G_TOPI 34816

__device__ __forceinline__ void cp_tile64(uint32_t sb, int dst, const __half* src, int tid){
    const char* s = (const char*)src;
#pragma unroll
    for (int i = tid; i < 512; i += 256){
        int row = i >> 3, ch = i & 7;
        uint32_t d = sb + dst + row*GSR + ch*16;
        asm volatile("cp.async.cg.shared.global [%0], [%1], 16;" :: "r"(d), "l"(s + i*16));
    }
}
__device__ __forceinline__ void cp_tile128(uint32_t sb, int dst, const __half* src, int tid){
    const char* s = (const char*)src;
#pragma unroll
    for (int i = tid; i < 1024; i += 256){
        int row = i >> 3, ch = i & 7;
        uint32_t d = sb + dst + row*GSR + ch*16;
        asm volatile("cp.async.cg.shared.global [%0], [%1], 16;" :: "r"(d), "l"(s + i*16));
    }
}

__global__ __launch_bounds__(256,2) void graph_kernel(const float* __restrict__ states)
{
    extern __shared__ char sm[];
    uint32_t sb = smem_u32(sm);
    int tid = threadIdx.x, wid = tid >> 5, lane = tid & 31;
    int bb = blockIdx.y, n0 = blockIdx.x * 64;
    size_t bofs = (size_t)bb*Nn*64;
    int tmin_sim = n0 >> 7;

    cp_tile64(sb, GA_QH, g_Qh + bofs + (size_t)n0*64, tid);
    cp_tile64(sb, GA_PH, g_Ph + bofs + (size_t)n0*64, tid);
    cp_tile128(sb, GB + GB_KH, g_Kh + bofs, tid);
    if (0 >= tmin_sim) cp_tile128(sb, GB + GB_PH, g_Ph + bofs, tid);
    CP_COMMIT();
    {
        size_t mofs = bofs + (size_t)128*64;
        cp_tile128(sb, GB + GB_BUF + GB_KH, g_Kh + mofs, tid);
        if (1 >= tmin_sim) cp_tile128(sb, GB + GB_BUF + GB_PH, g_Ph + mofs, tid);
        CP_COMMIT();
    }

    int wm = (wid & 3)*16, wn0 = (wid >> 2)*64, wng = wid >> 2;
    int rql = lane >> 2, cq = (lane & 3)*2, j4 = lane & 3;

    float v0[8], v1[8]; int i0[8], i1[8];
#pragma unroll
    for (int j = 0; j < 8; j++){ v0[j]=-1e30f; v1[j]=-1e30f; i0[j]=0; i1[j]=0; }

    for (int t = 0; t < Nn/128; t++){
        int buf = t & 1;
        if (t + 1 < Nn/128) CP_WAIT1(); else CP_WAIT0();
        __syncthreads();
        uint32_t bB = sb + GB + buf*GB_BUF;

        // ---- pass 1: scores = Qh . Kh ----
        float acc[8][4];
#pragma unroll
        for (int nt = 0; nt < 8; nt++)
#pragma unroll
            for (int e = 0; e < 4; e++) acc[nt][e] = 0.f;
#pragma unroll
        for (int kc = 0; kc < 4; kc++){
            uint32_t ah[4];
            ldmA(sb + GA_QH, wm, kc, GSR, ah);
            uint32_t bf[4][4];
#pragma unroll
            for (int p = 0; p < 4; p++) ldmB4(bB + GB_KH, wn0 + p*16, kc, GSR, bf[p]);
#pragma unroll
            for (int nt = 0; nt < 8; nt++) mma_h(acc[nt], ah, &bf[nt>>1][(nt&1)*2]);
        }
        {
            float t0 = -1e30f, t1 = -1e30f;
#pragma unroll
            for (int nt = 0; nt < 8; nt++){
                t0 = fmaxf(t0, fmaxf(acc[nt][0], acc[nt][1]));
                t1 = fmaxf(t1, fmaxf(acc[nt][2], acc[nt][3]));
            }
            if (t0 > v0[7]){
#pragma unroll
                for (int nt = 0; nt < 8; nt++){
                    int cb = t*128 + wn0 + nt*8 + cq;
                    INS8(v0, i0, acc[nt][0], cb);
                    INS8(v0, i0, acc[nt][1], cb+1);
                }
            }
            if (t1 > v1[7]){
#pragma unroll
                for (int nt = 0; nt < 8; nt++){
                    int cb = t*128 + wn0 + nt*8 + cq;
                    INS8(v1, i1, acc[nt][2], cb);
                    INS8(v1, i1, acc[nt][3], cb+1);
                }
            }
        }

        // ---- pass 2: sim = Ph . Ph (upper triangle, gated checks) ----
        if (t >= tmin_sim){
#pragma unroll
            for (int nt = 0; nt < 8; nt++)
#pragma unroll
                for (int e = 0; e < 4; e++) acc[nt][e] = 0.f;
#pragma unroll
            for (int kc = 0; kc < 4; kc++){
                uint32_t ah[4];
                ldmA(sb + GA_PH, wm, kc, GSR, ah);
                uint32_t bf[4][4];
#pragma unroll
                for (int p = 0; p < 4; p++) ldmB4(bB + GB_PH, wn0 + p*16, kc, GSR, bf[p]);
#pragma unroll
                for (int nt = 0; nt < 8; nt++) mma_h(acc[nt], ah, &bf[nt>>1][(nt&1)*2]);
            }
            // single-compare gate: only scan elements when some sim > 0.7
            float tmax = -1e30f;
#pragma unroll
            for (int nt = 0; nt < 8; nt++){
                tmax = fmaxf(tmax, fmaxf(fmaxf(acc[nt][0], acc[nt][1]),
                                         fmaxf(acc[nt][2], acc[nt][3])));
            }
            if (tmax > 0.7f){
#pragma unroll
                for (int nt = 0; nt < 8; nt++)
#pragma unroll
                    for (int e = 0; e < 4; e++){
                        if (acc[nt][e] > 0.7f){
                            int row = n0 + wm + rql + ((e >= 2) ? 8 : 0);
                            int col = t*128 + wn0 + nt*8 + cq + (e & 1);
                            if (col >= row){
                                int hr = bb*Nn + row;
                                int s1 = atomicAdd(&g_hitcnt[hr], 1);
                                if (s1 < 32) g_hitlist[(size_t)hr*32 + s1] = col;
                                if (col > row){
                                    int hc = bb*Nn + col;
                                    int s2 = atomicAdd(&g_hitcnt[hc], 1);
                                    if (s2 < 32) g_hitlist[(size_t)hc*32 + s2] = row;
                                }
                            }
                        }
                    }
            }
        }
        __syncthreads();

        if (t + 2 < Nn/128){
            size_t mofs = bofs + (size_t)(t+2)*128*64;
            cp_tile128(sb, GB + buf*GB_BUF + GB_KH, g_Kh + mofs, tid);
            if (t + 2 >= tmin_sim) cp_tile128(sb, GB + buf*GB_BUF + GB_PH, g_Ph + mofs, tid);
            CP_COMMIT();
        }
    }
    __syncthreads();

    // ---- dump candidates: 8 slices/row x 8 = 64 per row ----
    int* candI = (int*)(sm + G_CANDI);
    {
        int r0 = wm + rql, r1 = wm + rql + 8;
        int slice = wng*4 + j4;
#pragma unroll
        for (int s = 0; s < 8; s++){
            candI[r0*64 + slice*8 + s] = i0[s];
            candI[r1*64 + slice*8 + s] = i1[s];
        }
    }
    __syncthreads();

    // ---- exact fp32 rescore: 4 threads/row x 16 candidates ----
    float* mergeV = (float*)(sm + G_MV);
    int*   mergeI = (int*)(sm + G_MI);
    {
        int row = tid >> 2, sub = tid & 3;
        const float4* Q4 = (const float4*)(g_Qf + bofs + (size_t)(n0 + row)*64);
        float q[64];
#pragma unroll
        for (int i = 0; i < 16; i++){
            float4 v = Q4[i];
            q[4*i] = v.x; q[4*i+1] = v.y; q[4*i+2] = v.z; q[4*i+3] = v.w;
        }
        float tv[8]; int ti8[8];
#pragma unroll
        for (int j = 0; j < 8; j++){ tv[j] = -1e30f; ti8[j] = 0; }
#pragma unroll
        for (int c = 0; c < 16; c++){
            int col = candI[row*64 + sub*16 + c];
            const float4* K4 = (const float4*)(g_Kf + bofs + (size_t)col*64);
            float a2 = 0.f;
#pragma unroll
            for (int i = 0; i < 16; i++){
                float4 kv = K4[i];
                a2 = fmaf(q[4*i],   kv.x, a2);
                a2 = fmaf(q[4*i+1], kv.y, a2);
                a2 = fmaf(q[4*i+2], kv.z, a2);
                a2 = fmaf(q[4*i+3], kv.w, a2);
            }
            a2 *= 0.125f;
            INS8(tv, ti8, a2, col);
        }
#pragma unroll
        for (int s = 0; s < 8; s++){
            mergeV[row*32 + sub*8 + s] = tv[s];
            mergeI[row*32 + sub*8 + s] = ti8[s];
        }
    }
    __syncthreads();

    // ---- final merge + softmax (64 threads) ----
    float* topW = (float*)(sm + G_TOPW);
    int*   topI = (int*)(sm + G_TOPI);
    if (tid < 64){
        float tv[8]; int ti8[8];
#pragma unroll
        for (int j = 0; j < 8; j++){ tv[j] = -1e30f; ti8[j] = 0; }
#pragma unroll
        for (int c = 0; c < 32; c++){
            float mv = mergeV[tid*32 + c];
            int  mi = mergeI[tid*32 + c];
            INS8(tv, ti8, mv, mi);
        }
        float mx = tv[0];
        float e[8], ssum = 0.f;
#pragma unroll
        for (int j = 0; j < 8; j++){ e[j] = __expf(tv[j] - mx); ssum += e[j]; }
        float inv = 1.f / ssum;
#pragma unroll
        for (int j = 0; j < 8; j++){ topW[tid*8+j] = e[j]*inv; topI[tid*8+j] = ti8[j]; }
    }
    __syncthreads();

    // ---- gather incoming (8 warps x 8 rows) ----
    const float* Sb = states + (size_t)bb*Nn*Dd;
    for (int rr = 0; rr < 8; rr++){
        int r = wid*8 + rr;
        float w8[8]; int i8[8];
#pragma unroll
        for (int j = 0; j < 8; j++){ w8[j] = topW[r*8+j]; i8[j] = topI[r*8+j]; }
        float* Ig = g_INC + ((size_t)bb*Nn + n0 + r)*Dd;
#pragma unroll
        for (int dd = 0; dd < 8; dd++){
            int d = lane + dd*32;
            float a2 = 0.f;
#pragma unroll
            for (int j = 0; j < 8; j++) a2 = fmaf(w8[j], Sb[(size_t)i8[j]*Dd + d], a2);
            Ig[d] = a2;
        }
    }
}

// ---------------- kernel 3a: phase-1 gather + X (fp16) ----------------
__global__ __launch_bounds__(256) void hdc_a(float* __restrict__ out_states){
    int tid = threadIdx.x, wid = tid >> 5, lane = tid & 31;
    int row0 = blockIdx.x * 64;
    int bb = row0 / Nn;
    for (int r8 = 0; r8 < 8; r8++){
        int row = row0 + wid*8 + r8;
        int cnt = g_hitcnt[row];
        int lim = cnt < 32 ? cnt : 32;
        const int* hl = g_hitlist + (size_t)row*32;
        float comb[8];
#pragma unroll
        for (int i = 0; i < 8; i++) comb[i] = 0.f;
        for (int j = 0; j < lim; j++){
            const float* src = g_INC + ((size_t)bb*Nn + hl[j])*Dd;
#pragma unroll
            for (int i = 0; i < 8; i++) comb[i] += src[lane + i*32];
        }
        const float* inc = g_INC + (size_t)row*Dd;
        float inv = 0.2f / ((float)cnt + 1e-8f);
#pragma unroll
        for (int i = 0; i < 8; i++){
            int d = lane + i*32;
            float ov = 0.8f*inc[d] + comb[i]*inv;
            out_states[(size_t)row*Dd + d] = ov;
            g_Xh[(size_t)row*Dd + d] = __float2half(ov);
        }
    }
    if (tid < 64){
        g_dot[row0+tid] = 0.f; g_na[row0+tid] = 0.f; g_nb[row0+tid] = 0.f;
    }
}

// ---------------- kernel 3b: Wh GEMM (fp16 single-term) + episodic -------
#define SR 144
#define HB_BUFSZ 27648
#define HB_AH 0
#define HB_BH 18432
#define HB_TOT 55296

__device__ __forceinline__ void cp_rows(uint32_t sb, int dst, const __half* src,
                                        int nrows, size_t srcstride, int tid){
    int total = nrows*8;
    for (int i = tid; i < total; i += 256){
        int row = i >> 3, ch = i & 7;
        uint32_t d = sb + dst + row*SR + ch*16;
        const char* s = (const char*)(src + (size_t)row*srcstride) + ch*16;
        asm volatile("cp.async.cg.shared.global [%0], [%1], 16;" :: "r"(d), "l"(s));
    }
}

__global__ __launch_bounds__(256,3) void hdc_b(
    const float* __restrict__ episodic,
    const float* __restrict__ bh,
    const float* __restrict__ keys, const float* __restrict__ pcodes,
    const int* __restrict__ step,
    float* __restrict__ out_epi)
{
    extern __shared__ char sm[];
    uint32_t sb = smem_u32(sm);
    int tid = threadIdx.x, wid = tid >> 5, lane = tid & 31;
    int row0 = blockIdx.x * 128;
    int c0   = blockIdx.y * 64;
    int prow = ((step[0] % NCc) + NCc) % NCc;
    const float* posr = pcodes + (size_t)prow*Hh;

    const __half* Xh = g_Xh + (size_t)row0*Dd;
    const __half* Wh = g_WhT + (size_t)c0*Dd;

    cp_rows(sb, HB_AH, Xh,      128, Dd, tid);
    cp_rows(sb, HB_BH, Wh,      64,  Dd, tid);
    CP_COMMIT();
    cp_rows(sb, HB_BUFSZ + HB_AH, Xh + 64, 128, Dd, tid);
    cp_rows(sb, HB_BUFSZ + HB_BH, Wh + 64, 64,  Dd, tid);
    CP_COMMIT();

    int wm = wid*16;
    int rql = lane >> 2, cq = (lane & 3)*2, j4 = lane & 3;

    float acc[8][4];
#pragma unroll
    for (int nt = 0; nt < 8; nt++)
#pragma unroll
        for (int e = 0; e < 4; e++) acc[nt][e] = 0.f;

    for (int c = 0; c < 4; c++){
        int buf = c & 1;
        if (c + 1 < 4) CP_WAIT1(); else CP_WAIT0();
        __syncthreads();
        uint32_t aH = sb + buf*HB_BUFSZ + HB_AH;
        uint32_t bH = sb + buf*HB_BUFSZ + HB_BH;
#pragma unroll
        for (int kc = 0; kc < 4; kc++){
            uint32_t ah[4];
            ldmA(aH, wm, kc, SR, ah);
            uint32_t bfh[4][4];
#pragma unroll
            for (int p = 0; p < 4; p++) ldmB4(bH, p*16, kc, SR, bfh[p]);
#pragma unroll
            for (int nt = 0; nt < 8; nt++) mma_h(acc[nt], ah, &bfh[nt>>1][(nt&1)*2]);
        }
        __syncthreads();
        if (c + 2 < 4){
            int koff = (c+2)*64;
            cp_rows(sb, buf*HB_BUFSZ + HB_AH, Xh + koff, 128, Dd, tid);
            cp_rows(sb, buf*HB_BUFSZ + HB_BH, Wh + koff, 64,  Dd, tid);
            CP_COMMIT();
        }
    }

    float d0 = 0.f, a0 = 0.f, b0 = 0.f;
    float d1 = 0.f, a1 = 0.f, b1 = 0.f;
    int grow0 = row0 + wm + rql, grow1 = grow0 + 8;
    int n0k = grow0 & (Nn-1), n1k = grow1 & (Nn-1);
#pragma unroll
    for (int nt = 0; nt < 8; nt++){
        int col = c0 + nt*8 + cq;
        float bh0 = __ldg(bh + col), bh1v = __ldg(bh + col + 1);
        float p0c = __ldg(posr + col), p1c = __ldg(posr + col + 1);
        {
            float y0 = 6.0f*(acc[nt][0] + bh0);
            float y1 = 6.0f*(acc[nt][1] + bh1v);
            float h0 = 1.0f - 2.0f/(__expf(y0) + 1.0f);
            float h1 = 1.0f - 2.0f/(__expf(y1) + 1.0f);
            float2 ky = *(const float2*)(keys + (size_t)n0k*Hh + col);
            float pe0 = h0*ky.x, pe1 = h1*ky.y;
            float2 ep = *(const float2*)(episodic + (size_t)grow0*Hh + col);
            float ne0 = 0.95f*ep.x + 0.05f*pe0*p0c;
            float ne1 = 0.95f*ep.y + 0.05f*pe1*p1c;
            *(float2*)(out_epi + (size_t)grow0*Hh + col) = make_float2(ne0, ne1);
            d0 = fmaf(ne0, pe0, fmaf(ne1, pe1, d0));
            a0 = fmaf(ne0, ne0, fmaf(ne1, ne1, a0));
            b0 = fmaf(pe0, pe0, fmaf(pe1, pe1, b0));
        }
        {
            float y0 = 6.0f*(acc[nt][2] + bh0);
            float y1 = 6.0f*(acc[nt][3] + bh1v);
            float h0 = 1.0f - 2.0f/(__expf(y0) + 1.0f);
            float h1 = 1.0f - 2.0f/(__expf(y1) + 1.0f);
            float2 ky = *(const float2*)(keys + (size_t)n1k*Hh + col);
            float pe0 = h0*ky.x, pe1 = h1*ky.y;
            float2 ep = *(const float2*)(episodic + (size_t)grow1*Hh + col);
            float ne0 = 0.95f*ep.x + 0.05f*pe0*p0c;
            float ne1 = 0.95f*ep.y + 0.05f*pe1*p1c;
            *(float2*)(out_epi + (size_t)grow1*Hh + col) = make_float2(ne0, ne1);
            d1 = fmaf(ne0, pe0, fmaf(ne1, pe1, d1));
            a1 = fmaf(ne0, ne0, fmaf(ne1, ne1, a1));
            b1 = fmaf(pe0, pe0, fmaf(pe1, pe1, b1));
        }
    }
#pragma unroll
    for (int off = 1; off <= 2; off <<= 1){
        d0 += __shfl_xor_sync(0xffffffffu, d0, off);
        a0 += __shfl_xor_sync(0xffffffffu, a0, off);
        b0 += __shfl_xor_sync(0xffffffffu, b0, off);
        d1 += __shfl_xor_sync(0xffffffffu, d1, off);
        a1 += __shfl_xor_sync(0xffffffffu, a1, off);
        b1 += __shfl_xor_sync(0xffffffffu, b1, off);
    }
    if (j4 == 0){
        atomicAdd(&g_dot[grow0], d0); atomicAdd(&g_na[grow0], a0); atomicAdd(&g_nb[grow0], b0);
        atomicAdd(&g_dot[grow1], d1); atomicAdd(&g_na[grow1], a1); atomicAdd(&g_nb[grow1], b1);
    }
}

// ---------------- kernel 3c: out_sim finisher ----------------
__global__ __launch_bounds__(256) void hdc_c(float* __restrict__ out_sim){
    int i = blockIdx.x*256 + threadIdx.x;
    out_sim[i] = g_dot[i] / (fmaxf(sqrtf(g_na[i]), 1e-8f)*fmaxf(sqrtf(g_nb[i]), 1e-8f));
}

// ---------------- launch ----------------
extern "C" void kernel_launch(void* const* d_in, const int* in_sizes, int n_in,
                              void* d_out, int out_size)
{
    (void)in_sizes; (void)n_in; (void)out_size;
    const float* states   = (const float*)d_in[0];
    const float* actions  = (const float*)d_in[1];
    const float* episodic = (const float*)d_in[2];
    const float* Wq = (const float*)d_in[3];  const float* bq = (const float*)d_in[4];
    const float* Wk = (const float*)d_in[5];  const float* bk = (const float*)d_in[6];
    const float* Wc = (const float*)d_in[7];  const float* bc = (const float*)d_in[8];
    const float* Wh = (const float*)d_in[9];  const float* bh = (const float*)d_in[10];
    const float* keys   = (const float*)d_in[11];
    const float* pcodes = (const float*)d_in[12];
    const int*   step   = (const int*)d_in[13];

    float* out = (float*)d_out;
    float* o_states = out;
    float* o_epi    = out + (size_t)BN*Dd;
    float* o_sim    = out + (size_t)BN*Dd + (size_t)BN*Hh;

    cudaFuncSetAttribute(proj_kernel, cudaFuncAttributeMaxDynamicSharedMemorySize, PJ_TOT);
    proj_kernel<<<PROJ_BLOCKS + WH_BLOCKS, 256, PJ_TOT>>>(actions, Wq, bq, Wk, bk, Wc, bc, Wh);

    cudaFuncSetAttribute(graph_kernel, cudaFuncAttributeMaxDynamicSharedMemorySize, G_TOT);
    graph_kernel<<<dim3(Nn/64, Bb), 256, G_TOT>>>(states);

    hdc_a<<<BN/64, 256>>>(o_states);

    cudaFuncSetAttribute(hdc_b, cudaFuncAttributeMaxDynamicSharedMemorySize, HB_TOT);
    hdc_b<<<dim3(BN/128, Hh/64), 256, HB_TOT>>>(episodic, bh, keys, pcodes, step, o_epi);

    hdc_c<<<BN/256, 256>>>(o_sim);
}